// round 6
// baseline (speedup 1.0000x reference)
#include <cuda_runtime.h>
#include <cuda_bf16.h>
#include <stdint.h>

#define MAXN 200000
#define MAXE 3200000
#define HD   128
#define MAXBLK 1024

// ---------------- scratch (device globals; no allocation allowed) ----------------
__device__ int   g_is32;
__device__ int   g_indeg[MAXN];
__device__ float g_dinv[MAXN];
__device__ int   g_rowptr[MAXN + 1];
__device__ int   g_cursor[MAXN];
__device__ int   g_col[MAXE];
__device__ int   g_src32[MAXE];
__device__ int   g_dst32[MAXE];
__device__ int   g_blockSums[MAXBLK];
__device__ int   g_blockOff[MAXBLK];
__device__ float g_bufA[(size_t)MAXN * HD];
__device__ float g_bufB[(size_t)MAXN * HD];

// packed f32x2 FMA: d = a*b + d  (dual fp32 path on sm_103a)
__device__ __forceinline__ void ffma2(float2& d, const float2 a, const float2 b) {
    asm("fma.rn.f32x2 %0, %1, %2, %0;"
        : "+l"(*reinterpret_cast<unsigned long long*>(&d))
        : "l"(*reinterpret_cast<const unsigned long long*>(&a)),
          "l"(*reinterpret_cast<const unsigned long long*>(&b)));
}

// ---------------- dtype detection: int64 vs int32 edge_index ----------------
__global__ void k_detect(const void* __restrict__ edge, int n) {
    if (threadIdx.x == 0 && blockIdx.x == 0) {
        const long long* e64 = (const long long*)edge;
        int is32 = 0;
        for (int i = 0; i < 64; i++) {
            long long v = e64[i];
            if (v < 0 || v >= (long long)n) { is32 = 1; break; }
        }
        g_is32 = is32;
    }
}

// ---------------- degree / edge conversion ----------------
__global__ void k_init_deg(int n) {
    int i = blockIdx.x * blockDim.x + threadIdx.x;
    if (i < n) g_indeg[i] = 0;
}

__global__ void k_count(const void* __restrict__ edge, int E, int n) {
    int e = blockIdx.x * blockDim.x + threadIdx.x;
    if (e >= E) return;
    int s, d;
    if (g_is32) {
        const int* e32 = (const int*)edge;
        s = e32[e];
        d = e32[e + E];
    } else {
        const long long* e64 = (const long long*)edge;
        s = (int)e64[e];
        d = (int)e64[e + E];
    }
    if ((unsigned)s >= (unsigned)n) s = 0;
    if ((unsigned)d >= (unsigned)n) d = 0;
    g_src32[e] = s;
    g_dst32[e] = d;
    atomicAdd(&g_indeg[d], 1);
}

__global__ void k_dinv(int n) {
    int i = blockIdx.x * blockDim.x + threadIdx.x;
    if (i < n) g_dinv[i] = rsqrtf((float)(g_indeg[i] + 1));
}

// ---------------- 3-stage exclusive scan of in-degrees -> rowptr ----------------
__global__ void k_scan1(int n) {
    __shared__ int s[256];
    int i = blockIdx.x * 256 + threadIdx.x;
    int v = (i < n) ? g_indeg[i] : 0;
    s[threadIdx.x] = v;
    __syncthreads();
    for (int off = 128; off > 0; off >>= 1) {
        if (threadIdx.x < off) s[threadIdx.x] += s[threadIdx.x + off];
        __syncthreads();
    }
    if (threadIdx.x == 0) g_blockSums[blockIdx.x] = s[0];
}

__global__ void k_scan2(int nb) {
    __shared__ int s[MAXBLK];
    int t = threadIdx.x;
    int v = (t < nb) ? g_blockSums[t] : 0;
    s[t] = v;
    __syncthreads();
    for (int off = 1; off < MAXBLK; off <<= 1) {
        int x = (t >= off) ? s[t - off] : 0;
        __syncthreads();
        s[t] += x;
        __syncthreads();
    }
    if (t < nb) g_blockOff[t] = s[t] - v;   // exclusive
}

__global__ void k_scan3(int n) {
    __shared__ int s[256];
    int t = threadIdx.x;
    int i = blockIdx.x * 256 + t;
    int v = (i < n) ? g_indeg[i] : 0;
    s[t] = v;
    __syncthreads();
    for (int off = 1; off < 256; off <<= 1) {
        int x = (t >= off) ? s[t - off] : 0;
        __syncthreads();
        s[t] += x;
        __syncthreads();
    }
    int excl = s[t] - v;
    int rp = g_blockOff[blockIdx.x] + excl;
    if (i < n) {
        g_rowptr[i] = rp;
        g_cursor[i] = rp;
        if (i == n - 1) g_rowptr[n] = rp + v;
    }
}

__global__ void k_fill(int E) {
    int e = blockIdx.x * blockDim.x + threadIdx.x;
    if (e < E) {
        int d = g_dst32[e];
        int pos = atomicAdd(&g_cursor[d], 1);
        g_col[pos] = g_src32[e];
    }
}

// ---------------- GEMM: Y[n,128] = X[n,fin] @ W[fin,128] ----------------
// Block-tiled: 128 rows x 128 cols per block, X read ONCE (no col-slice grid).
// 256 threads, each owns 2 rows x 32 cols as 32 f32x2 accumulators.
// K staged in 32-wide tiles: Xs transposed [k][row] (pad 129), Ws [k][col].
__global__ void __launch_bounds__(256, 2)
k_gemm(const float* __restrict__ X, const float* __restrict__ W,
       float* __restrict__ Y, int n, int fin) {
    __shared__ float Xs[32 * 129];
    __shared__ float Ws[32 * 128];

    const int tid = threadIdx.x;
    const int cs = tid & 3;          // col slice: [cs*32, cs*32+32)
    const int rp = tid >> 2;         // row pair: rows 2rp, 2rp+1
    const int rbase = blockIdx.x * 128;

    float2 a0[16], a1[16];
#pragma unroll
    for (int j = 0; j < 16; j++) {
        a0[j] = make_float2(0.f, 0.f);
        a1[j] = make_float2(0.f, 0.f);
    }

    const int nkt = (fin + 31) >> 5;
    for (int kt = 0; kt < nkt; kt++) {
        const int kbase = kt << 5;
        // stage X tile (128 rows x 32 k), transposed with pad
        for (int i = tid; i < 4096; i += 256) {
            int row = i >> 5, col = i & 31;
            int gr = rbase + row, gk = kbase + col;
            float v = (gr < n && gk < fin) ? __ldg(&X[(size_t)gr * fin + gk]) : 0.f;
            Xs[col * 129 + row] = v;
        }
        // stage W tile (32 k x 128 cols)
        for (int i = tid; i < 4096; i += 256) {
            int k = i >> 7, c = i & 127;
            int gk = kbase + k;
            Ws[k * 128 + c] = (gk < fin) ? __ldg(&W[(size_t)gk * HD + c]) : 0.f;
        }
        __syncthreads();

#pragma unroll 4
        for (int kk = 0; kk < 32; kk++) {
            float x0 = Xs[kk * 129 + 2 * rp];
            float x1 = Xs[kk * 129 + 2 * rp + 1];
            float2 xa = make_float2(x0, x0);
            float2 xb = make_float2(x1, x1);
            const float4* wr4 = (const float4*)(Ws + kk * 128 + cs * 32);
#pragma unroll
            for (int j = 0; j < 8; j++) {
                float4 w = wr4[j];
                float2 wlo = make_float2(w.x, w.y);
                float2 whi = make_float2(w.z, w.w);
                ffma2(a0[2 * j + 0], xa, wlo);
                ffma2(a0[2 * j + 1], xa, whi);
                ffma2(a1[2 * j + 0], xb, wlo);
                ffma2(a1[2 * j + 1], xb, whi);
            }
        }
        __syncthreads();
    }

    int r0 = rbase + 2 * rp;
    int r1 = r0 + 1;
    if (r0 < n) {
        float4* yp = (float4*)(Y + (size_t)r0 * HD + cs * 32);
#pragma unroll
        for (int j = 0; j < 8; j++)
            yp[j] = make_float4(a0[2 * j].x, a0[2 * j].y, a0[2 * j + 1].x, a0[2 * j + 1].y);
    }
    if (r1 < n) {
        float4* yp = (float4*)(Y + (size_t)r1 * HD + cs * 32);
#pragma unroll
        for (int j = 0; j < 8; j++)
            yp[j] = make_float4(a1[2 * j].x, a1[2 * j].y, a1[2 * j + 1].x, a1[2 * j + 1].y);
    }
}

// ---------------- Aggregation core: one warp per node, CSR gather, unroll-8 ----------------
__device__ __forceinline__ float4 agg_node(const float4* __restrict__ H4,
                                           int node, int lane, float di,
                                           const float4 b4) {
    int s0 = g_rowptr[node];
    int s1 = g_rowptr[node + 1];

    float4 acc = make_float4(0.f, 0.f, 0.f, 0.f);
    float4 acc2 = make_float4(0.f, 0.f, 0.f, 0.f);

    int e = s0;
    for (; e + 8 <= s1; e += 8) {
        int i0 = __ldg(&g_col[e + 0]);
        int i1 = __ldg(&g_col[e + 1]);
        int i2 = __ldg(&g_col[e + 2]);
        int i3 = __ldg(&g_col[e + 3]);
        int i4 = __ldg(&g_col[e + 4]);
        int i5 = __ldg(&g_col[e + 5]);
        int i6 = __ldg(&g_col[e + 6]);
        int i7 = __ldg(&g_col[e + 7]);
        float c0 = __ldg(&g_dinv[i0]);
        float c1 = __ldg(&g_dinv[i1]);
        float c2 = __ldg(&g_dinv[i2]);
        float c3 = __ldg(&g_dinv[i3]);
        float c4 = __ldg(&g_dinv[i4]);
        float c5 = __ldg(&g_dinv[i5]);
        float c6 = __ldg(&g_dinv[i6]);
        float c7 = __ldg(&g_dinv[i7]);
        float4 v0 = H4[(size_t)i0 * 32 + lane];
        float4 v1 = H4[(size_t)i1 * 32 + lane];
        float4 v2 = H4[(size_t)i2 * 32 + lane];
        float4 v3 = H4[(size_t)i3 * 32 + lane];
        float4 v4 = H4[(size_t)i4 * 32 + lane];
        float4 v5 = H4[(size_t)i5 * 32 + lane];
        float4 v6 = H4[(size_t)i6 * 32 + lane];
        float4 v7 = H4[(size_t)i7 * 32 + lane];
        acc.x = fmaf(c0, v0.x, acc.x); acc.y = fmaf(c0, v0.y, acc.y);
        acc.z = fmaf(c0, v0.z, acc.z); acc.w = fmaf(c0, v0.w, acc.w);
        acc2.x = fmaf(c1, v1.x, acc2.x); acc2.y = fmaf(c1, v1.y, acc2.y);
        acc2.z = fmaf(c1, v1.z, acc2.z); acc2.w = fmaf(c1, v1.w, acc2.w);
        acc.x = fmaf(c2, v2.x, acc.x); acc.y = fmaf(c2, v2.y, acc.y);
        acc.z = fmaf(c2, v2.z, acc.z); acc.w = fmaf(c2, v2.w, acc.w);
        acc2.x = fmaf(c3, v3.x, acc2.x); acc2.y = fmaf(c3, v3.y, acc2.y);
        acc2.z = fmaf(c3, v3.z, acc2.z); acc2.w = fmaf(c3, v3.w, acc2.w);
        acc.x = fmaf(c4, v4.x, acc.x); acc.y = fmaf(c4, v4.y, acc.y);
        acc.z = fmaf(c4, v4.z, acc.z); acc.w = fmaf(c4, v4.w, acc.w);
        acc2.x = fmaf(c5, v5.x, acc2.x); acc2.y = fmaf(c5, v5.y, acc2.y);
        acc2.z = fmaf(c5, v5.z, acc2.z); acc2.w = fmaf(c5, v5.w, acc2.w);
        acc.x = fmaf(c6, v6.x, acc.x); acc.y = fmaf(c6, v6.y, acc.y);
        acc.z = fmaf(c6, v6.z, acc.z); acc.w = fmaf(c6, v6.w, acc.w);
        acc2.x = fmaf(c7, v7.x, acc2.x); acc2.y = fmaf(c7, v7.y, acc2.y);
        acc2.z = fmaf(c7, v7.z, acc2.z); acc2.w = fmaf(c7, v7.w, acc2.w);
    }
    for (; e < s1; e++) {
        int s = __ldg(&g_col[e]);
        float cs = __ldg(&g_dinv[s]);
        float4 v = H4[(size_t)s * 32 + lane];
        acc.x = fmaf(cs, v.x, acc.x); acc.y = fmaf(cs, v.y, acc.y);
        acc.z = fmaf(cs, v.z, acc.z); acc.w = fmaf(cs, v.w, acc.w);
    }
    acc.x += acc2.x; acc.y += acc2.y; acc.z += acc2.z; acc.w += acc2.w;

    float4 hv = H4[(size_t)node * 32 + lane];
    float dd = di * di;
    float4 r;
    r.x = fmaf(di, acc.x, fmaf(dd, hv.x, b4.x));
    r.y = fmaf(di, acc.y, fmaf(dd, hv.y, b4.y));
    r.z = fmaf(di, acc.z, fmaf(dd, hv.z, b4.z));
    r.w = fmaf(di, acc.w, fmaf(dd, hv.w, b4.w));
    r.x = fmaxf(r.x, 0.f); r.y = fmaxf(r.y, 0.f);
    r.z = fmaxf(r.z, 0.f); r.w = fmaxf(r.w, 0.f);
    return r;
}

// layer-1 aggregation: write full relu(h) row
__global__ void k_agg(const float* __restrict__ Hin, float* __restrict__ Hout,
                      const float* __restrict__ bias, int n) {
    int gt = blockIdx.x * blockDim.x + threadIdx.x;
    int node = gt >> 5;
    int lane = gt & 31;
    if (node >= n) return;
    float di = g_dinv[node];
    float4 b4 = ((const float4*)bias)[lane];
    float4 r = agg_node((const float4*)Hin, node, lane, di, b4);
    ((float4*)Hout)[(size_t)node * 32 + lane] = r;
}

// layer-2 aggregation fused with the linear head: write out[n,2] only
__global__ void k_agg_head(const float* __restrict__ Hin,
                           const float* __restrict__ bias,
                           const float* __restrict__ Wl,
                           const float* __restrict__ bl,
                           float* __restrict__ out, int n) {
    int gt = blockIdx.x * blockDim.x + threadIdx.x;
    int node = gt >> 5;
    int lane = gt & 31;
    if (node >= n) return;
    float di = g_dinv[node];
    float4 b4 = ((const float4*)bias)[lane];
    float4 r = agg_node((const float4*)Hin, node, lane, di, b4);

    // head: lane covers cols 4*lane .. 4*lane+3
    const float4* Wl4 = (const float4*)Wl;
    float4 w01 = __ldg(&Wl4[2 * lane + 0]);
    float4 w23 = __ldg(&Wl4[2 * lane + 1]);
    float a0 = r.x * w01.x + r.y * w01.z + r.z * w23.x + r.w * w23.z;
    float a1 = r.x * w01.y + r.y * w01.w + r.z * w23.y + r.w * w23.w;
#pragma unroll
    for (int off = 16; off > 0; off >>= 1) {
        a0 += __shfl_down_sync(0xffffffffu, a0, off);
        a1 += __shfl_down_sync(0xffffffffu, a1, off);
    }
    if (lane == 0) {
        out[2 * node + 0] = a0 + __ldg(&bl[0]);
        out[2 * node + 1] = a1 + __ldg(&bl[1]);
    }
}

// ---------------- launch ----------------
extern "C" void kernel_launch(void* const* d_in, const int* in_sizes, int n_in,
                              void* d_out, int out_size) {
    const float* x   = (const float*)d_in[0];
    const void*  edge = d_in[1];
    const float* W1  = (const float*)d_in[2];
    const float* b1  = (const float*)d_in[3];
    const float* W2  = (const float*)d_in[4];
    const float* b2  = (const float*)d_in[5];
    const float* Wl  = (const float*)d_in[6];
    const float* bl  = (const float*)d_in[7];
    float* out = (float*)d_out;

    int fin = in_sizes[2] / HD;            // 165
    int n   = in_sizes[0] / fin;           // 200000
    int E   = in_sizes[1] / 2;             // 3200000

    float* bufA; float* bufB;
    cudaGetSymbolAddress((void**)&bufA, g_bufA);
    cudaGetSymbolAddress((void**)&bufB, g_bufB);

    int nb = (n + 255) / 256;              // 782 <= MAXBLK
    int gemm_blocks = (n + 127) / 128;

    // launch order keeps the heavy layer-1 k_gemm at ncu's captured slot (4th)
    k_detect<<<1, 32>>>(edge, n);
    k_init_deg<<<nb, 256>>>(n);
    k_count<<<(E + 255) / 256, 256>>>(edge, E, n);

    k_gemm<<<gemm_blocks, 256>>>(x, W1, bufA, n, fin);   // layer-1 GEMM

    k_dinv<<<nb, 256>>>(n);
    k_scan1<<<nb, 256>>>(n);
    k_scan2<<<1, MAXBLK>>>(nb);
    k_scan3<<<nb, 256>>>(n);
    k_fill<<<(E + 255) / 256, 256>>>(E);

    long long tot = (long long)n * 32;
    k_agg<<<(unsigned)((tot + 255) / 256), 256>>>(bufA, bufB, b1, n);
    k_gemm<<<gemm_blocks, 256>>>(bufB, W2, bufA, n, HD);
    k_agg_head<<<(unsigned)((tot + 255) / 256), 256>>>(bufA, b2, Wl, bl, out, n);
}

// round 8
// speedup vs baseline: 1.3017x; 1.3017x over previous
#include <cuda_runtime.h>
#include <cuda_bf16.h>
#include <stdint.h>

#define MAXN 200000
#define MAXE 3200000
#define HD   128
#define MAXBLK 1024

// ---------------- scratch (device globals; no allocation allowed) ----------------
__device__ int   g_is32;
__device__ int   g_indeg[MAXN];
__device__ float g_dinv[MAXN];
__device__ int   g_rowptr[MAXN + 1];
__device__ int   g_cursor[MAXN];
__device__ int   g_col[MAXE];
__device__ int   g_src32[MAXE];
__device__ int   g_dst32[MAXE];
__device__ int   g_blockSums[MAXBLK];
__device__ int   g_blockOff[MAXBLK];
__device__ float g_bufA[(size_t)MAXN * HD];
__device__ float g_bufB[(size_t)MAXN * HD];

// packed f32x2 FMA: d = a*b + d  (dual fp32 path on sm_103a)
__device__ __forceinline__ void ffma2(float2& d, const float2 a, const float2 b) {
    asm("fma.rn.f32x2 %0, %1, %2, %0;"
        : "+l"(*reinterpret_cast<unsigned long long*>(&d))
        : "l"(*reinterpret_cast<const unsigned long long*>(&a)),
          "l"(*reinterpret_cast<const unsigned long long*>(&b)));
}

// ---------------- dtype detection: int64 vs int32 edge_index ----------------
__global__ void k_detect(const void* __restrict__ edge, int n) {
    if (threadIdx.x == 0 && blockIdx.x == 0) {
        const long long* e64 = (const long long*)edge;
        int is32 = 0;
        for (int i = 0; i < 64; i++) {
            long long v = e64[i];
            if (v < 0 || v >= (long long)n) { is32 = 1; break; }
        }
        g_is32 = is32;
    }
}

// ---------------- degree / edge conversion ----------------
__global__ void k_init_deg(int n) {
    int i = blockIdx.x * blockDim.x + threadIdx.x;
    if (i < n) g_indeg[i] = 0;
}

__global__ void k_count(const void* __restrict__ edge, int E, int n) {
    int e = blockIdx.x * blockDim.x + threadIdx.x;
    if (e >= E) return;
    int s, d;
    if (g_is32) {
        const int* e32 = (const int*)edge;
        s = e32[e];
        d = e32[e + E];
    } else {
        const long long* e64 = (const long long*)edge;
        s = (int)e64[e];
        d = (int)e64[e + E];
    }
    if ((unsigned)s >= (unsigned)n) s = 0;
    if ((unsigned)d >= (unsigned)n) d = 0;
    g_src32[e] = s;
    g_dst32[e] = d;
    atomicAdd(&g_indeg[d], 1);
}

__global__ void k_dinv(int n) {
    int i = blockIdx.x * blockDim.x + threadIdx.x;
    if (i < n) g_dinv[i] = rsqrtf((float)(g_indeg[i] + 1));
}

// ---------------- 3-stage exclusive scan of in-degrees -> rowptr ----------------
__global__ void k_scan1(int n) {
    __shared__ int s[256];
    int i = blockIdx.x * 256 + threadIdx.x;
    int v = (i < n) ? g_indeg[i] : 0;
    s[threadIdx.x] = v;
    __syncthreads();
    for (int off = 128; off > 0; off >>= 1) {
        if (threadIdx.x < off) s[threadIdx.x] += s[threadIdx.x + off];
        __syncthreads();
    }
    if (threadIdx.x == 0) g_blockSums[blockIdx.x] = s[0];
}

__global__ void k_scan2(int nb) {
    __shared__ int s[MAXBLK];
    int t = threadIdx.x;
    int v = (t < nb) ? g_blockSums[t] : 0;
    s[t] = v;
    __syncthreads();
    for (int off = 1; off < MAXBLK; off <<= 1) {
        int x = (t >= off) ? s[t - off] : 0;
        __syncthreads();
        s[t] += x;
        __syncthreads();
    }
    if (t < nb) g_blockOff[t] = s[t] - v;   // exclusive
}

__global__ void k_scan3(int n) {
    __shared__ int s[256];
    int t = threadIdx.x;
    int i = blockIdx.x * 256 + t;
    int v = (i < n) ? g_indeg[i] : 0;
    s[t] = v;
    __syncthreads();
    for (int off = 1; off < 256; off <<= 1) {
        int x = (t >= off) ? s[t - off] : 0;
        __syncthreads();
        s[t] += x;
        __syncthreads();
    }
    int excl = s[t] - v;
    int rp = g_blockOff[blockIdx.x] + excl;
    if (i < n) {
        g_rowptr[i] = rp;
        g_cursor[i] = rp;
        if (i == n - 1) g_rowptr[n] = rp + v;
    }
}

__global__ void k_fill(int E) {
    int e = blockIdx.x * blockDim.x + threadIdx.x;
    if (e < E) {
        int d = g_dst32[e];
        int pos = atomicAdd(&g_cursor[d], 1);
        g_col[pos] = g_src32[e];
    }
}

// ---------------- GEMM: Y[n,128] = X[n,fin] @ W[fin,128] ----------------
// Block tile: 256 rows x 128 cols. 256 threads, each owns 4 rows x 32 cols
// (64 f32x2 accumulators). Per k-step: 4 broadcast LDS + 8 LDS.128 vs
// 128 SMSP-cycles of FFMA2 -> FMA-issue-bound, X read once (coalesced).
__global__ void __launch_bounds__(256, 1)
k_gemm(const float* __restrict__ X, const float* __restrict__ W,
       float* __restrict__ Y, int n, int fin) {
    __shared__ float Xs[32 * 257];   // [k][row] with pad (bank-conflict-free)
    __shared__ float Ws[32 * 128];   // [k][col]

    const int tid = threadIdx.x;
    const int cs = tid & 3;          // col slice: [cs*32, cs*32+32)
    const int rq = tid >> 2;         // row quad: rows 4rq..4rq+3 (0..63)
    const int rbase = blockIdx.x * 256;

    float2 acc[4][16];
#pragma unroll
    for (int r = 0; r < 4; r++)
#pragma unroll
        for (int j = 0; j < 16; j++) acc[r][j] = make_float2(0.f, 0.f);

    const int nkt = (fin + 31) >> 5;
    for (int kt = 0; kt < nkt; kt++) {
        const int kbase = kt << 5;
        // stage X tile (256 rows x 32 k), transposed, coalesced 128B reads
        for (int i = tid; i < 8192; i += 256) {
            int row = i >> 5, col = i & 31;
            int gr = rbase + row, gk = kbase + col;
            float v = (gr < n && gk < fin) ? __ldg(&X[(size_t)gr * fin + gk]) : 0.f;
            Xs[col * 257 + row] = v;
        }
        // stage W tile (32 k x 128 cols)
        for (int i = tid; i < 4096; i += 256) {
            int k = i >> 7, c = i & 127;
            int gk = kbase + k;
            Ws[k * 128 + c] = (gk < fin) ? __ldg(&W[(size_t)gk * HD + c]) : 0.f;
        }
        __syncthreads();

        for (int kk = 0; kk < 32; kk++) {
            const float* xr = Xs + kk * 257 + 4 * rq;
            float x0 = xr[0], x1 = xr[1], x2 = xr[2], x3 = xr[3];
            const float4* wr4 = (const float4*)(Ws + kk * 128 + cs * 32);
            float2 wp[16];
#pragma unroll
            for (int j = 0; j < 8; j++) {
                float4 w = wr4[j];
                wp[2 * j + 0] = make_float2(w.x, w.y);
                wp[2 * j + 1] = make_float2(w.z, w.w);
            }
            float2 xa = make_float2(x0, x0);
            float2 xb = make_float2(x1, x1);
            float2 xc = make_float2(x2, x2);
            float2 xd = make_float2(x3, x3);
#pragma unroll
            for (int j = 0; j < 16; j++) {
                ffma2(acc[0][j], xa, wp[j]);
                ffma2(acc[1][j], xb, wp[j]);
                ffma2(acc[2][j], xc, wp[j]);
                ffma2(acc[3][j], xd, wp[j]);
            }
        }
        __syncthreads();
    }

#pragma unroll
    for (int r = 0; r < 4; r++) {
        int row = rbase + 4 * rq + r;
        if (row < n) {
            float4* yp = (float4*)(Y + (size_t)row * HD + cs * 32);
#pragma unroll
            for (int j = 0; j < 8; j++)
                yp[j] = make_float4(acc[r][2 * j].x, acc[r][2 * j].y,
                                    acc[r][2 * j + 1].x, acc[r][2 * j + 1].y);
        }
    }
}

// ---------------- Aggregation core: one warp per node, CSR gather, unroll-8 ----------------
__device__ __forceinline__ float4 agg_node(const float4* __restrict__ H4,
                                           int node, int lane, float di,
                                           const float4 b4) {
    int s0 = g_rowptr[node];
    int s1 = g_rowptr[node + 1];

    float4 acc = make_float4(0.f, 0.f, 0.f, 0.f);
    float4 acc2 = make_float4(0.f, 0.f, 0.f, 0.f);

    int e = s0;
    for (; e + 8 <= s1; e += 8) {
        int i0 = __ldg(&g_col[e + 0]);
        int i1 = __ldg(&g_col[e + 1]);
        int i2 = __ldg(&g_col[e + 2]);
        int i3 = __ldg(&g_col[e + 3]);
        int i4 = __ldg(&g_col[e + 4]);
        int i5 = __ldg(&g_col[e + 5]);
        int i6 = __ldg(&g_col[e + 6]);
        int i7 = __ldg(&g_col[e + 7]);
        float c0 = __ldg(&g_dinv[i0]);
        float c1 = __ldg(&g_dinv[i1]);
        float c2 = __ldg(&g_dinv[i2]);
        float c3 = __ldg(&g_dinv[i3]);
        float c4 = __ldg(&g_dinv[i4]);
        float c5 = __ldg(&g_dinv[i5]);
        float c6 = __ldg(&g_dinv[i6]);
        float c7 = __ldg(&g_dinv[i7]);
        float4 v0 = H4[(size_t)i0 * 32 + lane];
        float4 v1 = H4[(size_t)i1 * 32 + lane];
        float4 v2 = H4[(size_t)i2 * 32 + lane];
        float4 v3 = H4[(size_t)i3 * 32 + lane];
        float4 v4 = H4[(size_t)i4 * 32 + lane];
        float4 v5 = H4[(size_t)i5 * 32 + lane];
        float4 v6 = H4[(size_t)i6 * 32 + lane];
        float4 v7 = H4[(size_t)i7 * 32 + lane];
        acc.x = fmaf(c0, v0.x, acc.x); acc.y = fmaf(c0, v0.y, acc.y);
        acc.z = fmaf(c0, v0.z, acc.z); acc.w = fmaf(c0, v0.w, acc.w);
        acc2.x = fmaf(c1, v1.x, acc2.x); acc2.y = fmaf(c1, v1.y, acc2.y);
        acc2.z = fmaf(c1, v1.z, acc2.z); acc2.w = fmaf(c1, v1.w, acc2.w);
        acc.x = fmaf(c2, v2.x, acc.x); acc.y = fmaf(c2, v2.y, acc.y);
        acc.z = fmaf(c2, v2.z, acc.z); acc.w = fmaf(c2, v2.w, acc.w);
        acc2.x = fmaf(c3, v3.x, acc2.x); acc2.y = fmaf(c3, v3.y, acc2.y);
        acc2.z = fmaf(c3, v3.z, acc2.z); acc2.w = fmaf(c3, v3.w, acc2.w);
        acc.x = fmaf(c4, v4.x, acc.x); acc.y = fmaf(c4, v4.y, acc.y);
        acc.z = fmaf(c4, v4.z, acc.z); acc.w = fmaf(c4, v4.w, acc.w);
        acc2.x = fmaf(c5, v5.x, acc2.x); acc2.y = fmaf(c5, v5.y, acc2.y);
        acc2.z = fmaf(c5, v5.z, acc2.z); acc2.w = fmaf(c5, v5.w, acc2.w);
        acc.x = fmaf(c6, v6.x, acc.x); acc.y = fmaf(c6, v6.y, acc.y);
        acc.z = fmaf(c6, v6.z, acc.z); acc.w = fmaf(c6, v6.w, acc.w);
        acc2.x = fmaf(c7, v7.x, acc2.x); acc2.y = fmaf(c7, v7.y, acc2.y);
        acc2.z = fmaf(c7, v7.z, acc2.z); acc2.w = fmaf(c7, v7.w, acc2.w);
    }
    for (; e < s1; e++) {
        int s = __ldg(&g_col[e]);
        float cs = __ldg(&g_dinv[s]);
        float4 v = H4[(size_t)s * 32 + lane];
        acc.x = fmaf(cs, v.x, acc.x); acc.y = fmaf(cs, v.y, acc.y);
        acc.z = fmaf(cs, v.z, acc.z); acc.w = fmaf(cs, v.w, acc.w);
    }
    acc.x += acc2.x; acc.y += acc2.y; acc.z += acc2.z; acc.w += acc2.w;

    float4 hv = H4[(size_t)node * 32 + lane];
    float dd = di * di;
    float4 r;
    r.x = fmaf(di, acc.x, fmaf(dd, hv.x, b4.x));
    r.y = fmaf(di, acc.y, fmaf(dd, hv.y, b4.y));
    r.z = fmaf(di, acc.z, fmaf(dd, hv.z, b4.z));
    r.w = fmaf(di, acc.w, fmaf(dd, hv.w, b4.w));
    r.x = fmaxf(r.x, 0.f); r.y = fmaxf(r.y, 0.f);
    r.z = fmaxf(r.z, 0.f); r.w = fmaxf(r.w, 0.f);
    return r;
}

// layer-1 aggregation: write full relu(h) row
__global__ void k_agg(const float* __restrict__ Hin, float* __restrict__ Hout,
                      const float* __restrict__ bias, int n) {
    int gt = blockIdx.x * blockDim.x + threadIdx.x;
    int node = gt >> 5;
    int lane = gt & 31;
    if (node >= n) return;
    float di = g_dinv[node];
    float4 b4 = ((const float4*)bias)[lane];
    float4 r = agg_node((const float4*)Hin, node, lane, di, b4);
    ((float4*)Hout)[(size_t)node * 32 + lane] = r;
}

// layer-2 aggregation fused with the linear head: write out[n,2] only
__global__ void k_agg_head(const float* __restrict__ Hin,
                           const float* __restrict__ bias,
                           const float* __restrict__ Wl,
                           const float* __restrict__ bl,
                           float* __restrict__ out, int n) {
    int gt = blockIdx.x * blockDim.x + threadIdx.x;
    int node = gt >> 5;
    int lane = gt & 31;
    if (node >= n) return;
    float di = g_dinv[node];
    float4 b4 = ((const float4*)bias)[lane];
    float4 r = agg_node((const float4*)Hin, node, lane, di, b4);

    // head: lane covers cols 4*lane .. 4*lane+3
    const float4* Wl4 = (const float4*)Wl;
    float4 w01 = __ldg(&Wl4[2 * lane + 0]);
    float4 w23 = __ldg(&Wl4[2 * lane + 1]);
    float a0 = r.x * w01.x + r.y * w01.z + r.z * w23.x + r.w * w23.z;
    float a1 = r.x * w01.y + r.y * w01.w + r.z * w23.y + r.w * w23.w;
#pragma unroll
    for (int off = 16; off > 0; off >>= 1) {
        a0 += __shfl_down_sync(0xffffffffu, a0, off);
        a1 += __shfl_down_sync(0xffffffffu, a1, off);
    }
    if (lane == 0) {
        out[2 * node + 0] = a0 + __ldg(&bl[0]);
        out[2 * node + 1] = a1 + __ldg(&bl[1]);
    }
}

// ---------------- launch ----------------
extern "C" void kernel_launch(void* const* d_in, const int* in_sizes, int n_in,
                              void* d_out, int out_size) {
    const float* x   = (const float*)d_in[0];
    const void*  edge = d_in[1];
    const float* W1  = (const float*)d_in[2];
    const float* b1  = (const float*)d_in[3];
    const float* W2  = (const float*)d_in[4];
    const float* b2  = (const float*)d_in[5];
    const float* Wl  = (const float*)d_in[6];
    const float* bl  = (const float*)d_in[7];
    float* out = (float*)d_out;

    int fin = in_sizes[2] / HD;            // 165
    int n   = in_sizes[0] / fin;           // 200000
    int E   = in_sizes[1] / 2;             // 3200000

    float* bufA; float* bufB;
    cudaGetSymbolAddress((void**)&bufA, g_bufA);
    cudaGetSymbolAddress((void**)&bufB, g_bufB);

    int nb = (n + 255) / 256;              // 782 <= MAXBLK
    int gemm_blocks = (n + 255) / 256;

    // launch order keeps the heavy layer-1 k_gemm at ncu's captured slot (4th)
    k_detect<<<1, 32>>>(edge, n);
    k_init_deg<<<nb, 256>>>(n);
    k_count<<<(E + 255) / 256, 256>>>(edge, E, n);

    k_gemm<<<gemm_blocks, 256>>>(x, W1, bufA, n, fin);   // layer-1 GEMM

    k_dinv<<<nb, 256>>>(n);
    k_scan1<<<nb, 256>>>(n);
    k_scan2<<<1, MAXBLK>>>(nb);
    k_scan3<<<nb, 256>>>(n);
    k_fill<<<(E + 255) / 256, 256>>>(E);

    long long tot = (long long)n * 32;
    k_agg<<<(unsigned)((tot + 255) / 256), 256>>>(bufA, bufB, b1, n);
    k_gemm<<<gemm_blocks, 256>>>(bufB, W2, bufA, n, HD);
    k_agg_head<<<(unsigned)((tot + 255) / 256), 256>>>(bufA, b2, Wl, bl, out, n);
}

// round 9
// speedup vs baseline: 2.8337x; 2.1770x over previous
#include <cuda_runtime.h>
#include <cuda_bf16.h>
#include <stdint.h>

#define MAXN 200000
#define MAXE 3200000
#define HD   128
#define MAXFIN 192
#define MAXBLK 1024

// ---------------- scratch (device globals; no allocation allowed) ----------------
__device__ int   g_is32;
__device__ int   g_indeg[MAXN];
__device__ float g_dinv[MAXN];
__device__ int   g_rowptr[MAXN + 1];
__device__ int   g_cursor[MAXN];
__device__ int   g_col[MAXE];
__device__ int   g_src32[MAXE];
__device__ int   g_dst32[MAXE];
__device__ int   g_blockSums[MAXBLK];
__device__ int   g_blockOff[MAXBLK];
__device__ float g_bufA[(size_t)MAXN * HD];
__device__ float g_bufB[(size_t)MAXN * HD];
__device__ float g_Whi[MAXFIN * HD];
__device__ float g_Wlo[MAXFIN * HD];

// ---------------- tf32 helpers ----------------
__device__ __forceinline__ uint32_t to_tf32(float x) {
    uint32_t r;
    asm("cvt.rna.tf32.f32 %0, %1;" : "=r"(r) : "f"(x));
    return r;
}

__device__ __forceinline__ void mma_tf32(float4& d, const uint32_t* a, const uint32_t* b) {
    asm volatile(
        "mma.sync.aligned.m16n8k8.row.col.f32.tf32.tf32.f32 "
        "{%0,%1,%2,%3}, {%4,%5,%6,%7}, {%8,%9}, {%0,%1,%2,%3};"
        : "+f"(d.x), "+f"(d.y), "+f"(d.z), "+f"(d.w)
        : "r"(a[0]), "r"(a[1]), "r"(a[2]), "r"(a[3]), "r"(b[0]), "r"(b[1]));
}

// ---------------- dtype detection: int64 vs int32 edge_index ----------------
__global__ void k_detect(const void* __restrict__ edge, int n) {
    if (threadIdx.x == 0 && blockIdx.x == 0) {
        const long long* e64 = (const long long*)edge;
        int is32 = 0;
        for (int i = 0; i < 64; i++) {
            long long v = e64[i];
            if (v < 0 || v >= (long long)n) { is32 = 1; break; }
        }
        g_is32 = is32;
    }
}

// ---------------- degree / edge conversion ----------------
__global__ void k_init_deg(int n) {
    int i = blockIdx.x * blockDim.x + threadIdx.x;
    if (i < n) g_indeg[i] = 0;
}

__global__ void k_count(const void* __restrict__ edge, int E, int n) {
    int e = blockIdx.x * blockDim.x + threadIdx.x;
    if (e >= E) return;
    int s, d;
    if (g_is32) {
        const int* e32 = (const int*)edge;
        s = e32[e];
        d = e32[e + E];
    } else {
        const long long* e64 = (const long long*)edge;
        s = (int)e64[e];
        d = (int)e64[e + E];
    }
    if ((unsigned)s >= (unsigned)n) s = 0;
    if ((unsigned)d >= (unsigned)n) d = 0;
    g_src32[e] = s;
    g_dst32[e] = d;
    atomicAdd(&g_indeg[d], 1);
}

__global__ void k_dinv(int n) {
    int i = blockIdx.x * blockDim.x + threadIdx.x;
    if (i < n) g_dinv[i] = rsqrtf((float)(g_indeg[i] + 1));
}

// ---------------- W split: W -> tf32 hi + tf32 lo (once per layer) ----------------
__global__ void k_wsplit(const float* __restrict__ W, int cnt) {
    int i = blockIdx.x * blockDim.x + threadIdx.x;
    if (i < cnt) {
        float w = W[i];
        float hi = __uint_as_float(to_tf32(w));
        float lo = __uint_as_float(to_tf32(w - hi));
        g_Whi[i] = hi;
        g_Wlo[i] = lo;
    }
}

// ---------------- 3-stage exclusive scan of in-degrees -> rowptr ----------------
__global__ void k_scan1(int n) {
    __shared__ int s[256];
    int i = blockIdx.x * 256 + threadIdx.x;
    int v = (i < n) ? g_indeg[i] : 0;
    s[threadIdx.x] = v;
    __syncthreads();
    for (int off = 128; off > 0; off >>= 1) {
        if (threadIdx.x < off) s[threadIdx.x] += s[threadIdx.x + off];
        __syncthreads();
    }
    if (threadIdx.x == 0) g_blockSums[blockIdx.x] = s[0];
}

__global__ void k_scan2(int nb) {
    __shared__ int s[MAXBLK];
    int t = threadIdx.x;
    int v = (t < nb) ? g_blockSums[t] : 0;
    s[t] = v;
    __syncthreads();
    for (int off = 1; off < MAXBLK; off <<= 1) {
        int x = (t >= off) ? s[t - off] : 0;
        __syncthreads();
        s[t] += x;
        __syncthreads();
    }
    if (t < nb) g_blockOff[t] = s[t] - v;   // exclusive
}

__global__ void k_scan3(int n) {
    __shared__ int s[256];
    int t = threadIdx.x;
    int i = blockIdx.x * 256 + t;
    int v = (i < n) ? g_indeg[i] : 0;
    s[t] = v;
    __syncthreads();
    for (int off = 1; off < 256; off <<= 1) {
        int x = (t >= off) ? s[t - off] : 0;
        __syncthreads();
        s[t] += x;
        __syncthreads();
    }
    int excl = s[t] - v;
    int rp = g_blockOff[blockIdx.x] + excl;
    if (i < n) {
        g_rowptr[i] = rp;
        g_cursor[i] = rp;
        if (i == n - 1) g_rowptr[n] = rp + v;
    }
}

__global__ void k_fill(int E) {
    int e = blockIdx.x * blockDim.x + threadIdx.x;
    if (e < E) {
        int d = g_dst32[e];
        int pos = atomicAdd(&g_cursor[d], 1);
        g_col[pos] = g_src32[e];
    }
}

// ---------------- GEMM: Y[n,128] = X[n,fin] @ W[fin,128] via tf32 MMA ----------------
// 3-term split precision: X=xh+xl, W=wh+wl; acc += xh*wh + xl*wh + xh*wl (fp32 acc).
// Block: 256 thr, tile 128x128, BK=32. Warp grid 2x4; warp tile 64x32.
// X staged fp32 (split in regs); W hi/lo pre-split in global, staged to smem.
// Pads (36/136) make every fragment LDS bank-conflict-free.
#define XS 36
#define WSD 136
__global__ void __launch_bounds__(256, 2)
k_gemm(const float* __restrict__ X, float* __restrict__ Y, int n, int fin) {
    extern __shared__ float sm[];
    float* Xs  = sm;                    // [128][XS]
    float* Whs = sm + 128 * XS;         // [32][WSD]
    float* Wls = Whs + 32 * WSD;        // [32][WSD]

    const int tid = threadIdx.x;
    const int wid = tid >> 5, lane = tid & 31;
    const int wm = wid >> 2, wn = wid & 3;       // warp grid 2 x 4
    const int lr = lane >> 2, lc = lane & 3;     // fragment row/col ids
    const int rbase = blockIdx.x * 128;

    float4 acc[4][4];
#pragma unroll
    for (int i = 0; i < 4; i++)
#pragma unroll
        for (int j = 0; j < 4; j++) acc[i][j] = make_float4(0.f, 0.f, 0.f, 0.f);

    const int nkt = (fin + 31) >> 5;
    for (int kt = 0; kt < nkt; kt++) {
        const int kbase = kt << 5;
        // stage X tile (128 rows x 32 k), coalesced
        for (int i = tid; i < 4096; i += 256) {
            int row = i >> 5, k = i & 31;
            int gr = rbase + row, gk = kbase + k;
            Xs[row * XS + k] = (gr < n && gk < fin) ? __ldg(&X[(size_t)gr * fin + gk]) : 0.f;
        }
        // stage W hi/lo tiles (32 k x 128 cols)
        for (int i = tid; i < 4096; i += 256) {
            int k = i >> 7, c = i & 127;
            int gk = kbase + k;
            float hv = 0.f, lv = 0.f;
            if (gk < fin) {
                hv = g_Whi[gk * HD + c];
                lv = g_Wlo[gk * HD + c];
            }
            Whs[k * WSD + c] = hv;
            Wls[k * WSD + c] = lv;
        }
        __syncthreads();

#pragma unroll
        for (int k8 = 0; k8 < 4; k8++) {
            const int kb = k8 * 8;
            uint32_t bh[4][2], bl[4][2];
#pragma unroll
            for (int na = 0; na < 4; na++) {
                int col = wn * 32 + na * 8 + lr;
                bh[na][0] = __float_as_uint(Whs[(kb + lc) * WSD + col]);
                bh[na][1] = __float_as_uint(Whs[(kb + lc + 4) * WSD + col]);
                bl[na][0] = __float_as_uint(Wls[(kb + lc) * WSD + col]);
                bl[na][1] = __float_as_uint(Wls[(kb + lc + 4) * WSD + col]);
            }
#pragma unroll
            for (int ma = 0; ma < 4; ma++) {
                int row = wm * 64 + ma * 16 + lr;
                float f0 = Xs[row * XS + kb + lc];
                float f1 = Xs[(row + 8) * XS + kb + lc];
                float f2 = Xs[row * XS + kb + lc + 4];
                float f3 = Xs[(row + 8) * XS + kb + lc + 4];
                uint32_t ah[4], al[4];
                ah[0] = to_tf32(f0); al[0] = to_tf32(f0 - __uint_as_float(ah[0]));
                ah[1] = to_tf32(f1); al[1] = to_tf32(f1 - __uint_as_float(ah[1]));
                ah[2] = to_tf32(f2); al[2] = to_tf32(f2 - __uint_as_float(ah[2]));
                ah[3] = to_tf32(f3); al[3] = to_tf32(f3 - __uint_as_float(ah[3]));
#pragma unroll
                for (int na = 0; na < 4; na++) {
                    mma_tf32(acc[ma][na], ah, bh[na]);
                    mma_tf32(acc[ma][na], al, bh[na]);
                    mma_tf32(acc[ma][na], ah, bl[na]);
                }
            }
        }
        __syncthreads();
    }

    // epilogue: c0,c1 -> (r, 2lc), (r, 2lc+1); c2,c3 -> row+8
#pragma unroll
    for (int ma = 0; ma < 4; ma++) {
        int r0 = rbase + wm * 64 + ma * 16 + lr;
#pragma unroll
        for (int na = 0; na < 4; na++) {
            int col = wn * 32 + na * 8 + 2 * lc;
            if (r0 < n)
                *(float2*)&Y[(size_t)r0 * HD + col] = make_float2(acc[ma][na].x, acc[ma][na].y);
            if (r0 + 8 < n)
                *(float2*)&Y[(size_t)(r0 + 8) * HD + col] = make_float2(acc[ma][na].z, acc[ma][na].w);
        }
    }
}
#define GEMM_SMEM (size_t)((128 * XS + 2 * 32 * WSD) * 4)

// ---------------- Aggregation core: one warp per node, CSR gather, unroll-8 ----------------
__device__ __forceinline__ float4 agg_node(const float4* __restrict__ H4,
                                           int node, int lane, float di,
                                           const float4 b4) {
    int s0 = g_rowptr[node];
    int s1 = g_rowptr[node + 1];

    float4 acc = make_float4(0.f, 0.f, 0.f, 0.f);
    float4 acc2 = make_float4(0.f, 0.f, 0.f, 0.f);

    int e = s0;
    for (; e + 8 <= s1; e += 8) {
        int i0 = __ldg(&g_col[e + 0]);
        int i1 = __ldg(&g_col[e + 1]);
        int i2 = __ldg(&g_col[e + 2]);
        int i3 = __ldg(&g_col[e + 3]);
        int i4 = __ldg(&g_col[e + 4]);
        int i5 = __ldg(&g_col[e + 5]);
        int i6 = __ldg(&g_col[e + 6]);
        int i7 = __ldg(&g_col[e + 7]);
        float c0 = __ldg(&g_dinv[i0]);
        float c1 = __ldg(&g_dinv[i1]);
        float c2 = __ldg(&g_dinv[i2]);
        float c3 = __ldg(&g_dinv[i3]);
        float c4 = __ldg(&g_dinv[i4]);
        float c5 = __ldg(&g_dinv[i5]);
        float c6 = __ldg(&g_dinv[i6]);
        float c7 = __ldg(&g_dinv[i7]);
        float4 v0 = H4[(size_t)i0 * 32 + lane];
        float4 v1 = H4[(size_t)i1 * 32 + lane];
        float4 v2 = H4[(size_t)i2 * 32 + lane];
        float4 v3 = H4[(size_t)i3 * 32 + lane];
        float4 v4 = H4[(size_t)i4 * 32 + lane];
        float4 v5 = H4[(size_t)i5 * 32 + lane];
        float4 v6 = H4[(size_t)i6 * 32 + lane];
        float4 v7 = H4[(size_t)i7 * 32 + lane];
        acc.x = fmaf(c0, v0.x, acc.x); acc.y = fmaf(c0, v0.y, acc.y);
        acc.z = fmaf(c0, v0.z, acc.z); acc.w = fmaf(c0, v0.w, acc.w);
        acc2.x = fmaf(c1, v1.x, acc2.x); acc2.y = fmaf(c1, v1.y, acc2.y);
        acc2.z = fmaf(c1, v1.z, acc2.z); acc2.w = fmaf(c1, v1.w, acc2.w);
        acc.x = fmaf(c2, v2.x, acc.x); acc.y = fmaf(c2, v2.y, acc.y);
        acc.z = fmaf(c2, v2.z, acc.z); acc.w = fmaf(c2, v2.w, acc.w);
        acc2.x = fmaf(c3, v3.x, acc2.x); acc2.y = fmaf(c3, v3.y, acc2.y);
        acc2.z = fmaf(c3, v3.z, acc2.z); acc2.w = fmaf(c3, v3.w, acc2.w);
        acc.x = fmaf(c4, v4.x, acc.x); acc.y = fmaf(c4, v4.y, acc.y);
        acc.z = fmaf(c4, v4.z, acc.z); acc.w = fmaf(c4, v4.w, acc.w);
        acc2.x = fmaf(c5, v5.x, acc2.x); acc2.y = fmaf(c5, v5.y, acc2.y);
        acc2.z = fmaf(c5, v5.z, acc2.z); acc2.w = fmaf(c5, v5.w, acc2.w);
        acc.x = fmaf(c6, v6.x, acc.x); acc.y = fmaf(c6, v6.y, acc.y);
        acc.z = fmaf(c6, v6.z, acc.z); acc.w = fmaf(c6, v6.w, acc.w);
        acc2.x = fmaf(c7, v7.x, acc2.x); acc2.y = fmaf(c7, v7.y, acc2.y);
        acc2.z = fmaf(c7, v7.z, acc2.z); acc2.w = fmaf(c7, v7.w, acc2.w);
    }
    for (; e < s1; e++) {
        int s = __ldg(&g_col[e]);
        float cs = __ldg(&g_dinv[s]);
        float4 v = H4[(size_t)s * 32 + lane];
        acc.x = fmaf(cs, v.x, acc.x); acc.y = fmaf(cs, v.y, acc.y);
        acc.z = fmaf(cs, v.z, acc.z); acc.w = fmaf(cs, v.w, acc.w);
    }
    acc.x += acc2.x; acc.y += acc2.y; acc.z += acc2.z; acc.w += acc2.w;

    float4 hv = H4[(size_t)node * 32 + lane];
    float dd = di * di;
    float4 r;
    r.x = fmaf(di, acc.x, fmaf(dd, hv.x, b4.x));
    r.y = fmaf(di, acc.y, fmaf(dd, hv.y, b4.y));
    r.z = fmaf(di, acc.z, fmaf(dd, hv.z, b4.z));
    r.w = fmaf(di, acc.w, fmaf(dd, hv.w, b4.w));
    r.x = fmaxf(r.x, 0.f); r.y = fmaxf(r.y, 0.f);
    r.z = fmaxf(r.z, 0.f); r.w = fmaxf(r.w, 0.f);
    return r;
}

// layer-1 aggregation: write full relu(h) row
__global__ void k_agg(const float* __restrict__ Hin, float* __restrict__ Hout,
                      const float* __restrict__ bias, int n) {
    int gt = blockIdx.x * blockDim.x + threadIdx.x;
    int node = gt >> 5;
    int lane = gt & 31;
    if (node >= n) return;
    float di = g_dinv[node];
    float4 b4 = ((const float4*)bias)[lane];
    float4 r = agg_node((const float4*)Hin, node, lane, di, b4);
    ((float4*)Hout)[(size_t)node * 32 + lane] = r;
}

// layer-2 aggregation fused with the linear head: write out[n,2] only
__global__ void k_agg_head(const float* __restrict__ Hin,
                           const float* __restrict__ bias,
                           const float* __restrict__ Wl,
                           const float* __restrict__ bl,
                           float* __restrict__ out, int n) {
    int gt = blockIdx.x * blockDim.x + threadIdx.x;
    int node = gt >> 5;
    int lane = gt & 31;
    if (node >= n) return;
    float di = g_dinv[node];
    float4 b4 = ((const float4*)bias)[lane];
    float4 r = agg_node((const float4*)Hin, node, lane, di, b4);

    // head: lane covers cols 4*lane .. 4*lane+3
    const float4* Wl4 = (const float4*)Wl;
    float4 w01 = __ldg(&Wl4[2 * lane + 0]);
    float4 w23 = __ldg(&Wl4[2 * lane + 1]);
    float a0 = r.x * w01.x + r.y * w01.z + r.z * w23.x + r.w * w23.z;
    float a1 = r.x * w01.y + r.y * w01.w + r.z * w23.y + r.w * w23.w;
#pragma unroll
    for (int off = 16; off > 0; off >>= 1) {
        a0 += __shfl_down_sync(0xffffffffu, a0, off);
        a1 += __shfl_down_sync(0xffffffffu, a1, off);
    }
    if (lane == 0) {
        out[2 * node + 0] = a0 + __ldg(&bl[0]);
        out[2 * node + 1] = a1 + __ldg(&bl[1]);
    }
}

// ---------------- launch ----------------
extern "C" void kernel_launch(void* const* d_in, const int* in_sizes, int n_in,
                              void* d_out, int out_size) {
    const float* x   = (const float*)d_in[0];
    const void*  edge = d_in[1];
    const float* W1  = (const float*)d_in[2];
    const float* b1  = (const float*)d_in[3];
    const float* W2  = (const float*)d_in[4];
    const float* b2  = (const float*)d_in[5];
    const float* Wl  = (const float*)d_in[6];
    const float* bl  = (const float*)d_in[7];
    float* out = (float*)d_out;

    int fin = in_sizes[2] / HD;            // 165
    int n   = in_sizes[0] / fin;           // 200000
    int E   = in_sizes[1] / 2;             // 3200000

    float* bufA; float* bufB;
    cudaGetSymbolAddress((void**)&bufA, g_bufA);
    cudaGetSymbolAddress((void**)&bufB, g_bufB);

    static int smem_set = 0;
    if (!smem_set) {
        cudaFuncSetAttribute(k_gemm, cudaFuncAttributeMaxDynamicSharedMemorySize,
                             (int)GEMM_SMEM);
        smem_set = 1;
    }

    int nb = (n + 255) / 256;              // 782 <= MAXBLK
    int gemm_blocks = (n + 127) / 128;

    // order keeps the heavy layer-1 k_gemm at ncu's captured slot (4th)
    k_detect<<<1, 32>>>(edge, n);
    k_init_deg<<<nb, 256>>>(n);
    k_wsplit<<<(fin * HD + 255) / 256, 256>>>(W1, fin * HD);

    k_gemm<<<gemm_blocks, 256, GEMM_SMEM>>>(x, bufA, n, fin);   // layer-1 GEMM

    k_count<<<(E + 255) / 256, 256>>>(edge, E, n);
    k_dinv<<<nb, 256>>>(n);
    k_scan1<<<nb, 256>>>(n);
    k_scan2<<<1, MAXBLK>>>(nb);
    k_scan3<<<nb, 256>>>(n);
    k_fill<<<(E + 255) / 256, 256>>>(E);

    long long tot = (long long)n * 32;
    k_agg<<<(unsigned)((tot + 255) / 256), 256>>>(bufA, bufB, b1, n);

    k_wsplit<<<(HD * HD + 255) / 256, 256>>>(W2, HD * HD);
    k_gemm<<<gemm_blocks, 256, GEMM_SMEM>>>(bufB, bufA, n, HD);
    k_agg_head<<<(unsigned)((tot + 255) / 256), 256>>>(bufA, b2, Wl, bl, out, n);
}

// round 10
// speedup vs baseline: 2.9216x; 1.0310x over previous
#include <cuda_runtime.h>
#include <cuda_bf16.h>
#include <stdint.h>

#define MAXN 200000
#define MAXE 3200000
#define HD   128
#define MAXFIN 192
#define MAXBLK 1024

// ---------------- scratch (device globals; no allocation allowed) ----------------
__device__ int   g_is32;
__device__ int   g_indeg[MAXN];
__device__ float g_dinv[MAXN];
__device__ int   g_rowptr[MAXN + 1];
__device__ int   g_cursor[MAXN];
__device__ int   g_col[MAXE];
__device__ int   g_src32[MAXE];
__device__ int   g_dst32[MAXE];
__device__ int   g_blockSums[MAXBLK];
__device__ int   g_blockOff[MAXBLK];
__device__ float g_bufA[(size_t)MAXN * HD];
__device__ float g_bufB[(size_t)MAXN * HD];
__device__ float g_Whi[MAXFIN * HD];
__device__ float g_Wlo[MAXFIN * HD];

// ---------------- tf32 helpers ----------------
__device__ __forceinline__ uint32_t to_tf32(float x) {
    uint32_t r;
    asm("cvt.rna.tf32.f32 %0, %1;" : "=r"(r) : "f"(x));
    return r;
}

__device__ __forceinline__ void mma_tf32(float4& d, const uint32_t* a, const uint32_t* b) {
    asm volatile(
        "mma.sync.aligned.m16n8k8.row.col.f32.tf32.tf32.f32 "
        "{%0,%1,%2,%3}, {%4,%5,%6,%7}, {%8,%9}, {%0,%1,%2,%3};"
        : "+f"(d.x), "+f"(d.y), "+f"(d.z), "+f"(d.w)
        : "r"(a[0]), "r"(a[1]), "r"(a[2]), "r"(a[3]), "r"(b[0]), "r"(b[1]));
}

// ---------------- dtype detection: int64 vs int32 edge_index ----------------
__global__ void k_detect(const void* __restrict__ edge, int n) {
    if (threadIdx.x == 0 && blockIdx.x == 0) {
        const long long* e64 = (const long long*)edge;
        int is32 = 0;
        for (int i = 0; i < 64; i++) {
            long long v = e64[i];
            if (v < 0 || v >= (long long)n) { is32 = 1; break; }
        }
        g_is32 = is32;
    }
}

// ---------------- degree / edge conversion ----------------
__global__ void k_init_deg(int n) {
    int i = blockIdx.x * blockDim.x + threadIdx.x;
    if (i < n) g_indeg[i] = 0;
}

__global__ void k_count(const void* __restrict__ edge, int E, int n) {
    int e = blockIdx.x * blockDim.x + threadIdx.x;
    if (e >= E) return;
    int s, d;
    if (g_is32) {
        const int* e32 = (const int*)edge;
        s = e32[e];
        d = e32[e + E];
    } else {
        const long long* e64 = (const long long*)edge;
        s = (int)e64[e];
        d = (int)e64[e + E];
    }
    if ((unsigned)s >= (unsigned)n) s = 0;
    if ((unsigned)d >= (unsigned)n) d = 0;
    g_src32[e] = s;
    g_dst32[e] = d;
    atomicAdd(&g_indeg[d], 1);
}

__global__ void k_dinv(int n) {
    int i = blockIdx.x * blockDim.x + threadIdx.x;
    if (i < n) g_dinv[i] = rsqrtf((float)(g_indeg[i] + 1));
}

// ---------------- W split: W -> tf32 hi + tf32 lo (once per layer) ----------------
__global__ void k_wsplit(const float* __restrict__ W, int cnt) {
    int i = blockIdx.x * blockDim.x + threadIdx.x;
    if (i < cnt) {
        float w = W[i];
        float hi = __uint_as_float(to_tf32(w));
        float lo = __uint_as_float(to_tf32(w - hi));
        g_Whi[i] = hi;
        g_Wlo[i] = lo;
    }
}

// ---------------- 3-stage exclusive scan of in-degrees -> rowptr ----------------
__global__ void k_scan1(int n) {
    __shared__ int s[256];
    int i = blockIdx.x * 256 + threadIdx.x;
    int v = (i < n) ? g_indeg[i] : 0;
    s[threadIdx.x] = v;
    __syncthreads();
    for (int off = 128; off > 0; off >>= 1) {
        if (threadIdx.x < off) s[threadIdx.x] += s[threadIdx.x + off];
        __syncthreads();
    }
    if (threadIdx.x == 0) g_blockSums[blockIdx.x] = s[0];
}

__global__ void k_scan2(int nb) {
    __shared__ int s[MAXBLK];
    int t = threadIdx.x;
    int v = (t < nb) ? g_blockSums[t] : 0;
    s[t] = v;
    __syncthreads();
    for (int off = 1; off < MAXBLK; off <<= 1) {
        int x = (t >= off) ? s[t - off] : 0;
        __syncthreads();
        s[t] += x;
        __syncthreads();
    }
    if (t < nb) g_blockOff[t] = s[t] - v;   // exclusive
}

__global__ void k_scan3(int n) {
    __shared__ int s[256];
    int t = threadIdx.x;
    int i = blockIdx.x * 256 + t;
    int v = (i < n) ? g_indeg[i] : 0;
    s[t] = v;
    __syncthreads();
    for (int off = 1; off < 256; off <<= 1) {
        int x = (t >= off) ? s[t - off] : 0;
        __syncthreads();
        s[t] += x;
        __syncthreads();
    }
    int excl = s[t] - v;
    int rp = g_blockOff[blockIdx.x] + excl;
    if (i < n) {
        g_rowptr[i] = rp;
        g_cursor[i] = rp;
        if (i == n - 1) g_rowptr[n] = rp + v;
    }
}

__global__ void k_fill(int E) {
    int e = blockIdx.x * blockDim.x + threadIdx.x;
    if (e < E) {
        int d = g_dst32[e];
        int pos = atomicAdd(&g_cursor[d], 1);
        g_col[pos] = g_src32[e];
    }
}

// ---------------- GEMM: Y[n,128] = X[n,fin] @ W[fin,128] via tf32 MMA ----------------
// 3-term split precision: X=xh+xl, W=wh+wl; acc += xh*wh + xl*wh + xh*wl (fp32 acc).
// X is split hi/lo ONCE at smem-stage time -> inner loop is pure LDS + HMMA.
// Block: 256 thr, tile 128x128, BK=32. Warp grid 2x4; warp tile 64x32.
#define XS 36
#define WSD 136
__global__ void __launch_bounds__(256, 2)
k_gemm(const float* __restrict__ X, float* __restrict__ Y, int n, int fin) {
    extern __shared__ float sm[];
    float* Xhs = sm;                    // [128][XS]
    float* Xls = Xhs + 128 * XS;        // [128][XS]
    float* Whs = Xls + 128 * XS;        // [32][WSD]
    float* Wls = Whs + 32 * WSD;        // [32][WSD]

    const int tid = threadIdx.x;
    const int wid = tid >> 5, lane = tid & 31;
    const int wm = wid >> 2, wn = wid & 3;       // warp grid 2 x 4
    const int lr = lane >> 2, lc = lane & 3;     // fragment row/col ids
    const int rbase = blockIdx.x * 128;

    float4 acc[4][4];
#pragma unroll
    for (int i = 0; i < 4; i++)
#pragma unroll
        for (int j = 0; j < 4; j++) acc[i][j] = make_float4(0.f, 0.f, 0.f, 0.f);

    const int nkt = (fin + 31) >> 5;
    for (int kt = 0; kt < nkt; kt++) {
        const int kbase = kt << 5;
        // stage X tile (128 rows x 32 k), coalesced; split hi/lo here once
        for (int i = tid; i < 4096; i += 256) {
            int row = i >> 5, k = i & 31;
            int gr = rbase + row, gk = kbase + k;
            float v = (gr < n && gk < fin) ? __ldg(&X[(size_t)gr * fin + gk]) : 0.f;
            float hi = __uint_as_float(to_tf32(v));
            float lo = __uint_as_float(to_tf32(v - hi));
            Xhs[row * XS + k] = hi;
            Xls[row * XS + k] = lo;
        }
        // stage W hi/lo tiles (32 k x 128 cols)
        for (int i = tid; i < 4096; i += 256) {
            int k = i >> 7, c = i & 127;
            int gk = kbase + k;
            float hv = 0.f, lv = 0.f;
            if (gk < fin) {
                hv = g_Whi[gk * HD + c];
                lv = g_Wlo[gk * HD + c];
            }
            Whs[k * WSD + c] = hv;
            Wls[k * WSD + c] = lv;
        }
        __syncthreads();

#pragma unroll
        for (int k8 = 0; k8 < 4; k8++) {
            const int kb = k8 * 8;
            uint32_t bh[4][2], bl[4][2];
#pragma unroll
            for (int na = 0; na < 4; na++) {
                int col = wn * 32 + na * 8 + lr;
                bh[na][0] = __float_as_uint(Whs[(kb + lc) * WSD + col]);
                bh[na][1] = __float_as_uint(Whs[(kb + lc + 4) * WSD + col]);
                bl[na][0] = __float_as_uint(Wls[(kb + lc) * WSD + col]);
                bl[na][1] = __float_as_uint(Wls[(kb + lc + 4) * WSD + col]);
            }
#pragma unroll
            for (int ma = 0; ma < 4; ma++) {
                int row = wm * 64 + ma * 16 + lr;
                uint32_t ah[4], al[4];
                ah[0] = __float_as_uint(Xhs[row * XS + kb + lc]);
                ah[1] = __float_as_uint(Xhs[(row + 8) * XS + kb + lc]);
                ah[2] = __float_as_uint(Xhs[row * XS + kb + lc + 4]);
                ah[3] = __float_as_uint(Xhs[(row + 8) * XS + kb + lc + 4]);
                al[0] = __float_as_uint(Xls[row * XS + kb + lc]);
                al[1] = __float_as_uint(Xls[(row + 8) * XS + kb + lc]);
                al[2] = __float_as_uint(Xls[row * XS + kb + lc + 4]);
                al[3] = __float_as_uint(Xls[(row + 8) * XS + kb + lc + 4]);
#pragma unroll
                for (int na = 0; na < 4; na++) {
                    mma_tf32(acc[ma][na], ah, bh[na]);
                    mma_tf32(acc[ma][na], al, bh[na]);
                    mma_tf32(acc[ma][na], ah, bl[na]);
                }
            }
        }
        __syncthreads();
    }

    // epilogue: c0,c1 -> (r, 2lc), (r, 2lc+1); c2,c3 -> row+8
#pragma unroll
    for (int ma = 0; ma < 4; ma++) {
        int r0 = rbase + wm * 64 + ma * 16 + lr;
#pragma unroll
        for (int na = 0; na < 4; na++) {
            int col = wn * 32 + na * 8 + 2 * lc;
            if (r0 < n)
                *(float2*)&Y[(size_t)r0 * HD + col] = make_float2(acc[ma][na].x, acc[ma][na].y);
            if (r0 + 8 < n)
                *(float2*)&Y[(size_t)(r0 + 8) * HD + col] = make_float2(acc[ma][na].z, acc[ma][na].w);
        }
    }
}
#define GEMM_SMEM (size_t)((2 * 128 * XS + 2 * 32 * WSD) * 4)

// ---------------- Aggregation core: one warp per node, CSR gather, unroll-8 ----------------
__device__ __forceinline__ float4 agg_node(const float4* __restrict__ H4,
                                           int node, int lane, float di,
                                           const float4 b4) {
    int s0 = g_rowptr[node];
    int s1 = g_rowptr[node + 1];

    float4 acc = make_float4(0.f, 0.f, 0.f, 0.f);
    float4 acc2 = make_float4(0.f, 0.f, 0.f, 0.f);

    int e = s0;
    for (; e + 8 <= s1; e += 8) {
        int i0 = __ldg(&g_col[e + 0]);
        int i1 = __ldg(&g_col[e + 1]);
        int i2 = __ldg(&g_col[e + 2]);
        int i3 = __ldg(&g_col[e + 3]);
        int i4 = __ldg(&g_col[e + 4]);
        int i5 = __ldg(&g_col[e + 5]);
        int i6 = __ldg(&g_col[e + 6]);
        int i7 = __ldg(&g_col[e + 7]);
        float c0 = __ldg(&g_dinv[i0]);
        float c1 = __ldg(&g_dinv[i1]);
        float c2 = __ldg(&g_dinv[i2]);
        float c3 = __ldg(&g_dinv[i3]);
        float c4 = __ldg(&g_dinv[i4]);
        float c5 = __ldg(&g_dinv[i5]);
        float c6 = __ldg(&g_dinv[i6]);
        float c7 = __ldg(&g_dinv[i7]);
        float4 v0 = H4[(size_t)i0 * 32 + lane];
        float4 v1 = H4[(size_t)i1 * 32 + lane];
        float4 v2 = H4[(size_t)i2 * 32 + lane];
        float4 v3 = H4[(size_t)i3 * 32 + lane];
        float4 v4 = H4[(size_t)i4 * 32 + lane];
        float4 v5 = H4[(size_t)i5 * 32 + lane];
        float4 v6 = H4[(size_t)i6 * 32 + lane];
        float4 v7 = H4[(size_t)i7 * 32 + lane];
        acc.x = fmaf(c0, v0.x, acc.x); acc.y = fmaf(c0, v0.y, acc.y);
        acc.z = fmaf(c0, v0.z, acc.z); acc.w = fmaf(c0, v0.w, acc.w);
        acc2.x = fmaf(c1, v1.x, acc2.x); acc2.y = fmaf(c1, v1.y, acc2.y);
        acc2.z = fmaf(c1, v1.z, acc2.z); acc2.w = fmaf(c1, v1.w, acc2.w);
        acc.x = fmaf(c2, v2.x, acc.x); acc.y = fmaf(c2, v2.y, acc.y);
        acc.z = fmaf(c2, v2.z, acc.z); acc.w = fmaf(c2, v2.w, acc.w);
        acc2.x = fmaf(c3, v3.x, acc2.x); acc2.y = fmaf(c3, v3.y, acc2.y);
        acc2.z = fmaf(c3, v3.z, acc2.z); acc2.w = fmaf(c3, v3.w, acc2.w);
        acc.x = fmaf(c4, v4.x, acc.x); acc.y = fmaf(c4, v4.y, acc.y);
        acc.z = fmaf(c4, v4.z, acc.z); acc.w = fmaf(c4, v4.w, acc.w);
        acc2.x = fmaf(c5, v5.x, acc2.x); acc2.y = fmaf(c5, v5.y, acc2.y);
        acc2.z = fmaf(c5, v5.z, acc2.z); acc2.w = fmaf(c5, v5.w, acc2.w);
        acc.x = fmaf(c6, v6.x, acc.x); acc.y = fmaf(c6, v6.y, acc.y);
        acc.z = fmaf(c6, v6.z, acc.z); acc.w = fmaf(c6, v6.w, acc.w);
        acc2.x = fmaf(c7, v7.x, acc2.x); acc2.y = fmaf(c7, v7.y, acc2.y);
        acc2.z = fmaf(c7, v7.z, acc2.z); acc2.w = fmaf(c7, v7.w, acc2.w);
    }
    for (; e < s1; e++) {
        int s = __ldg(&g_col[e]);
        float cs = __ldg(&g_dinv[s]);
        float4 v = H4[(size_t)s * 32 + lane];
        acc.x = fmaf(cs, v.x, acc.x); acc.y = fmaf(cs, v.y, acc.y);
        acc.z = fmaf(cs, v.z, acc.z); acc.w = fmaf(cs, v.w, acc.w);
    }
    acc.x += acc2.x; acc.y += acc2.y; acc.z += acc2.z; acc.w += acc2.w;

    float4 hv = H4[(size_t)node * 32 + lane];
    float dd = di * di;
    float4 r;
    r.x = fmaf(di, acc.x, fmaf(dd, hv.x, b4.x));
    r.y = fmaf(di, acc.y, fmaf(dd, hv.y, b4.y));
    r.z = fmaf(di, acc.z, fmaf(dd, hv.z, b4.z));
    r.w = fmaf(di, acc.w, fmaf(dd, hv.w, b4.w));
    r.x = fmaxf(r.x, 0.f); r.y = fmaxf(r.y, 0.f);
    r.z = fmaxf(r.z, 0.f); r.w = fmaxf(r.w, 0.f);
    return r;
}

// layer-1 aggregation: write full relu(h) row
__global__ void k_agg(const float* __restrict__ Hin, float* __restrict__ Hout,
                      const float* __restrict__ bias, int n) {
    int gt = blockIdx.x * blockDim.x + threadIdx.x;
    int node = gt >> 5;
    int lane = gt & 31;
    if (node >= n) return;
    float di = g_dinv[node];
    float4 b4 = ((const float4*)bias)[lane];
    float4 r = agg_node((const float4*)Hin, node, lane, di, b4);
    ((float4*)Hout)[(size_t)node * 32 + lane] = r;
}

// layer-2 aggregation fused with the linear head: write out[n,2] only
__global__ void k_agg_head(const float* __restrict__ Hin,
                           const float* __restrict__ bias,
                           const float* __restrict__ Wl,
                           const float* __restrict__ bl,
                           float* __restrict__ out, int n) {
    int gt = blockIdx.x * blockDim.x + threadIdx.x;
    int node = gt >> 5;
    int lane = gt & 31;
    if (node >= n) return;
    float di = g_dinv[node];
    float4 b4 = ((const float4*)bias)[lane];
    float4 r = agg_node((const float4*)Hin, node, lane, di, b4);

    // head: lane covers cols 4*lane .. 4*lane+3
    const float4* Wl4 = (const float4*)Wl;
    float4 w01 = __ldg(&Wl4[2 * lane + 0]);
    float4 w23 = __ldg(&Wl4[2 * lane + 1]);
    float a0 = r.x * w01.x + r.y * w01.z + r.z * w23.x + r.w * w23.z;
    float a1 = r.x * w01.y + r.y * w01.w + r.z * w23.y + r.w * w23.w;
#pragma unroll
    for (int off = 16; off > 0; off >>= 1) {
        a0 += __shfl_down_sync(0xffffffffu, a0, off);
        a1 += __shfl_down_sync(0xffffffffu, a1, off);
    }
    if (lane == 0) {
        out[2 * node + 0] = a0 + __ldg(&bl[0]);
        out[2 * node + 1] = a1 + __ldg(&bl[1]);
    }
}

// ---------------- launch ----------------
extern "C" void kernel_launch(void* const* d_in, const int* in_sizes, int n_in,
                              void* d_out, int out_size) {
    const float* x   = (const float*)d_in[0];
    const void*  edge = d_in[1];
    const float* W1  = (const float*)d_in[2];
    const float* b1  = (const float*)d_in[3];
    const float* W2  = (const float*)d_in[4];
    const float* b2  = (const float*)d_in[5];
    const float* Wl  = (const float*)d_in[6];
    const float* bl  = (const float*)d_in[7];
    float* out = (float*)d_out;

    int fin = in_sizes[2] / HD;            // 165
    int n   = in_sizes[0] / fin;           // 200000
    int E   = in_sizes[1] / 2;             // 3200000

    float* bufA; float* bufB;
    cudaGetSymbolAddress((void**)&bufA, g_bufA);
    cudaGetSymbolAddress((void**)&bufB, g_bufB);

    static int smem_set = 0;
    if (!smem_set) {
        cudaFuncSetAttribute(k_gemm, cudaFuncAttributeMaxDynamicSharedMemorySize,
                             (int)GEMM_SMEM);
        smem_set = 1;
    }

    int nb = (n + 255) / 256;              // 782 <= MAXBLK
    int gemm_blocks = (n + 127) / 128;

    // order keeps the heavy layer-1 k_gemm at ncu's captured slot (4th)
    k_detect<<<1, 32>>>(edge, n);
    k_init_deg<<<nb, 256>>>(n);
    k_wsplit<<<(fin * HD + 255) / 256, 256>>>(W1, fin * HD);

    k_gemm<<<gemm_blocks, 256, GEMM_SMEM>>>(x, bufA, n, fin);   // layer-1 GEMM

    k_count<<<(E + 255) / 256, 256>>>(edge, E, n);
    k_dinv<<<nb, 256>>>(n);
    k_scan1<<<nb, 256>>>(n);
    k_scan2<<<1, MAXBLK>>>(nb);
    k_scan3<<<nb, 256>>>(n);
    k_fill<<<(E + 255) / 256, 256>>>(E);

    long long tot = (long long)n * 32;
    k_agg<<<(unsigned)((tot + 255) / 256), 256>>>(bufA, bufB, b1, n);

    k_wsplit<<<(HD * HD + 255) / 256, 256>>>(W2, HD * HD);
    k_gemm<<<gemm_blocks, 256, GEMM_SMEM>>>(bufB, bufA, n, HD);
    k_agg_head<<<(unsigned)((tot + 255) / 256), 256>>>(bufA, b2, Wl, bl, out, n);
}